// round 3
// baseline (speedup 1.0000x reference)
#include <cuda_runtime.h>
#include <math.h>

// ---------------- scratch (static device globals; no allocation) ----------------
__device__ float g_buf1[32u*128*128*64];   // conv1 out   (reused A then B)
__device__ float g_buf2[32u*64*64*128];    // conv2 out
__device__ float g_buf3[32u*32*32*256];    // conv3 out
__device__ float g_featA[32u*256*512];     // normalized feat A (16x16x512)
__device__ float g_featB[32u*256*512];     // normalized feat B
__device__ float g_corr[32u*256*256];      // correlation (b, ij, kl)
__device__ float g_r1[32u*10*10*128];
__device__ float g_r2[32u*6*6*64];
__device__ float g_geo[32*18];

// ---------------- conv1: 256x256x3 -> 128x128x64, stride 2, SAME(pad_lo=0) ----
__global__ void conv1_kernel(const float* __restrict__ in, const float* __restrict__ w,
                             float* __restrict__ out)
{
    int idx = blockIdx.x * 256 + threadIdx.x;
    int oc = idx & 63;
    int p  = idx >> 6;
    int ow = p & 127; p >>= 7;
    int oh = p & 127; p >>= 7;
    int b  = p;                       // 0..31
    float acc = 0.f;
    #pragma unroll
    for (int kh = 0; kh < 3; ++kh) {
        int ih = oh * 2 + kh;
        if (ih >= 256) continue;
        #pragma unroll
        for (int kw = 0; kw < 3; ++kw) {
            int iw = ow * 2 + kw;
            if (iw >= 256) continue;
            const float* ip = in + ((size_t)(b * 256 + ih) * 256 + iw) * 3;
            const float* wp = w + ((kh * 3 + kw) * 3) * 64 + oc;
            acc += ip[0] * wp[0] + ip[1] * wp[64] + ip[2] * wp[128];
        }
    }
    out[idx] = fmaxf(acc, 0.f);
}

// ---------------- implicit-GEMM conv: BM=64, BN=64, BK=64, 4x4 microkernel ----
// Layout: in (img, HIN, WIN, CIN), weights (KH, KW, CIN, COUT), out (img, HOUT, WOUT, COUT)
// Padding: pad_lo = 0 for all layers used (SAME pad_total=1 -> lo=0,hi=1; VALID -> 0).
template<int CIN,int COUT,int HIN,int WIN,int HOUT,int WOUT,int KH,int KW,int STRIDE,bool MGUARD>
__global__ __launch_bounds__(256)
void conv_igemm(const float* __restrict__ in, const float* __restrict__ wt,
                float* __restrict__ out)
{
    constexpr int M   = HOUT * WOUT;
    constexpr int CPT = CIN / 64;          // k-chunks per filter tap
    constexpr int KCH = KH * KW * CPT;     // total 64-wide k-chunks
    __shared__ __align__(16) float As[64][68];  // k-major: As[k][m]
    __shared__ __align__(16) float Bs[64][68];  // k-major: Bs[k][n]

    int tid = threadIdx.x;
    int m0 = blockIdx.x * 64, n0 = blockIdx.y * 64;
    int img = blockIdx.z;
    const float* inb = in + (size_t)img * HIN * WIN * CIN;

    int lr = tid >> 2;               // 0..63
    int lc = (tid & 3) << 4;         // 0,16,32,48
    int m  = m0 + lr;
    int oh = m / WOUT, ow = m % WOUT;
    int ty = tid >> 4, tx = tid & 15;

    float acc[4][4] = {};

    for (int c = 0; c < KCH; ++c) {
        int tap  = c / CPT;
        int cin0 = (c % CPT) * 64;
        int kh = tap / KW, kw = tap - kh * KW;
        int ih = oh * STRIDE + kh, iw = ow * STRIDE + kw;
        bool ok = (ih < HIN) && (iw < WIN);
        if (MGUARD) ok = ok && (m < M);
        const float* ap = inb + ((size_t)ih * WIN + iw) * CIN + cin0 + lc;
        #pragma unroll
        for (int t = 0; t < 4; ++t) {
            float4 v = ok ? *reinterpret_cast<const float4*>(ap + 4 * t)
                          : make_float4(0.f, 0.f, 0.f, 0.f);
            As[lc + 4*t + 0][lr] = v.x; As[lc + 4*t + 1][lr] = v.y;
            As[lc + 4*t + 2][lr] = v.z; As[lc + 4*t + 3][lr] = v.w;
        }
        const float* bp = wt + ((size_t)tap * CIN + cin0 + lr) * COUT + n0 + lc;
        #pragma unroll
        for (int t = 0; t < 4; ++t)
            *reinterpret_cast<float4*>(&Bs[lr][lc + 4*t]) =
                *reinterpret_cast<const float4*>(bp + 4 * t);
        __syncthreads();

        #pragma unroll
        for (int kk = 0; kk < 64; ++kk) {
            float4 av = *reinterpret_cast<const float4*>(&As[kk][ty * 4]);
            float4 bv = *reinterpret_cast<const float4*>(&Bs[kk][tx * 4]);
            float ar[4] = {av.x, av.y, av.z, av.w};
            float br[4] = {bv.x, bv.y, bv.z, bv.w};
            #pragma unroll
            for (int i = 0; i < 4; ++i)
                #pragma unroll
                for (int j = 0; j < 4; ++j)
                    acc[i][j] += ar[i] * br[j];
        }
        __syncthreads();
    }

    #pragma unroll
    for (int i = 0; i < 4; ++i) {
        int mm = m0 + ty * 4 + i;
        if (MGUARD && mm >= M) continue;
        float4 v = make_float4(fmaxf(acc[i][0], 0.f), fmaxf(acc[i][1], 0.f),
                               fmaxf(acc[i][2], 0.f), fmaxf(acc[i][3], 0.f));
        *reinterpret_cast<float4*>(out + ((size_t)img * M + mm) * COUT + n0 + tx * 4) = v;
    }
}

// ---------------- correlation: C[b][m][n] = fA[b][m][:].fB[b][n][:], K=512 ----
__global__ __launch_bounds__(256)
void corr_kernel(const float* __restrict__ fA, const float* __restrict__ fB,
                 float* __restrict__ out)
{
    __shared__ __align__(16) float As[64][68];
    __shared__ __align__(16) float Bs[64][68];
    int tid = threadIdx.x;
    int m0 = blockIdx.x * 64, n0 = blockIdx.y * 64;
    int img = blockIdx.z;
    int lr = tid >> 2, lc = (tid & 3) << 4;
    int ty = tid >> 4, tx = tid & 15;
    float acc[4][4] = {};

    for (int c = 0; c < 8; ++c) {
        const float* ap = fA + ((size_t)img * 256 + m0 + lr) * 512 + c * 64 + lc;
        const float* bp = fB + ((size_t)img * 256 + n0 + lr) * 512 + c * 64 + lc;
        #pragma unroll
        for (int t = 0; t < 4; ++t) {
            float4 v = *reinterpret_cast<const float4*>(ap + 4 * t);
            As[lc + 4*t + 0][lr] = v.x; As[lc + 4*t + 1][lr] = v.y;
            As[lc + 4*t + 2][lr] = v.z; As[lc + 4*t + 3][lr] = v.w;
            float4 u = *reinterpret_cast<const float4*>(bp + 4 * t);
            Bs[lc + 4*t + 0][lr] = u.x; Bs[lc + 4*t + 1][lr] = u.y;
            Bs[lc + 4*t + 2][lr] = u.z; Bs[lc + 4*t + 3][lr] = u.w;
        }
        __syncthreads();
        #pragma unroll
        for (int kk = 0; kk < 64; ++kk) {
            float4 av = *reinterpret_cast<const float4*>(&As[kk][ty * 4]);
            float4 bv = *reinterpret_cast<const float4*>(&Bs[kk][tx * 4]);
            float ar[4] = {av.x, av.y, av.z, av.w};
            float br[4] = {bv.x, bv.y, bv.z, bv.w};
            #pragma unroll
            for (int i = 0; i < 4; ++i)
                #pragma unroll
                for (int j = 0; j < 4; ++j)
                    acc[i][j] += ar[i] * br[j];
        }
        __syncthreads();
    }
    #pragma unroll
    for (int i = 0; i < 4; ++i) {
        int mm = m0 + ty * 4 + i;
        float4 v = make_float4(acc[i][0], acc[i][1], acc[i][2], acc[i][3]);
        *reinterpret_cast<float4*>(out + ((size_t)img * 256 + mm) * 256 + n0 + tx * 4) = v;
    }
}

// ---------------- L2-normalize over 512 channels: x /= (||x|| + 1e-6) ----------
__global__ void normalize_kernel(float* __restrict__ feat)
{
    float* p = feat + (size_t)blockIdx.x * 512;
    int tid = threadIdx.x;   // 128
    float v0 = p[tid], v1 = p[tid + 128], v2 = p[tid + 256], v3 = p[tid + 384];
    float s = v0*v0 + v1*v1 + v2*v2 + v3*v3;
    for (int o = 16; o > 0; o >>= 1) s += __shfl_down_sync(0xffffffffu, s, o);
    __shared__ float sw[4];
    __shared__ float sscale;
    if ((tid & 31) == 0) sw[tid >> 5] = s;
    __syncthreads();
    if (tid == 0) sscale = 1.f / (sqrtf(sw[0] + sw[1] + sw[2] + sw[3]) + 1e-6f);
    __syncthreads();
    float sc = sscale;
    p[tid] = v0 * sc; p[tid + 128] = v1 * sc; p[tid + 256] = v2 * sc; p[tid + 384] = v3 * sc;
}

// ---------------- dense: geo = r2_flat(2304) @ Wd(2304,18) + bd ---------------
__global__ void dense_kernel(const float* __restrict__ x, const float* __restrict__ Wd,
                             const float* __restrict__ bd, float* __restrict__ geo)
{
    int b = blockIdx.x;
    int o = threadIdx.x >> 5;      // 0..17 (18 warps)
    int lane = threadIdx.x & 31;
    const float* xb = x + b * 2304;
    float acc = 0.f;
    for (int t = lane; t < 2304; t += 32)
        acc += xb[t] * Wd[t * 18 + o];
    for (int s = 16; s > 0; s >>= 1) acc += __shfl_down_sync(0xffffffffu, acc, s);
    if (lane == 0) geo[b * 18 + o] = acc + bd[o];
}

// ---------------- TPS fit + masked sum (fused final reduction) ----------------
// out[b] = sum_{k,l} sum_{|i-ay[k,l]|<=1, |j-ax[k,l]|<=1} corr[b, i*16+j, k*16+l]
__global__ void tps_sum_kernel(const float* __restrict__ geo, const float* __restrict__ corr,
                               float* __restrict__ out)
{
    int b = blockIdx.x, tid = threadIdx.x;   // 256 threads = 16x16 grid points
    __shared__ float sdx[9], sdy[9], swx[9], swy[9], sax[3], say[3];
    __shared__ float red[256];

    if (tid == 0) {
        const float srcx[9] = {0.f, 0.5f, 1.f, 0.f, 0.5f, 1.f, 0.f, 5.f, 1.f};
        const float srcy[9] = {0.f, 0.f,  0.f, 0.5f,0.5f, 0.5f,1.f, 1.f, 1.f};
        float dx9[9], dy9[9], vx[9], vy[9];
        for (int c = 0; c < 9; ++c) {
            float mx_ = geo[b * 18 + 2 * c], my_ = geo[b * 18 + 2 * c + 1];
            dx9[c] = srcx[c] + mx_;  dy9[c] = srcy[c] + my_;
            vx[c] = -mx_;            vy[c] = -my_;     // SRC - dst
        }
        // Build 12x12 TPS system with two RHS, solve via LU w/ partial pivoting.
        float Mx[12][14];
        for (int i = 0; i < 12; ++i)
            for (int j = 0; j < 14; ++j) Mx[i][j] = 0.f;
        for (int i = 0; i < 9; ++i) {
            for (int j = 0; j < 9; ++j) {
                float ddx = dx9[i] - dx9[j], ddy = dy9[i] - dy9[j];
                float r = sqrtf(ddx * ddx + ddy * ddy + 1e-12f);
                Mx[i][j] = r * r * logf(r + 1e-6f);
            }
            Mx[i][9] = 1.f; Mx[i][10] = dx9[i]; Mx[i][11] = dy9[i];
            Mx[9][i] = 1.f; Mx[10][i] = dx9[i]; Mx[11][i] = dy9[i];
            Mx[i][12] = vx[i]; Mx[i][13] = vy[i];
        }
        for (int k = 0; k < 12; ++k) {
            int piv = k; float best = fabsf(Mx[k][k]);
            for (int i = k + 1; i < 12; ++i) {
                float a = fabsf(Mx[i][k]);
                if (a > best) { best = a; piv = i; }
            }
            if (piv != k)
                for (int j = k; j < 14; ++j) {
                    float t = Mx[k][j]; Mx[k][j] = Mx[piv][j]; Mx[piv][j] = t;
                }
            for (int i = k + 1; i < 12; ++i) {
                float f = Mx[i][k] / Mx[k][k];
                for (int j = k + 1; j < 14; ++j) Mx[i][j] -= f * Mx[k][j];
                Mx[i][k] = 0.f;
            }
        }
        float thx[12], thy[12];
        for (int k = 11; k >= 0; --k) {
            float sx = Mx[k][12], sy = Mx[k][13];
            for (int j = k + 1; j < 12; ++j) { sx -= Mx[k][j] * thx[j]; sy -= Mx[k][j] * thy[j]; }
            thx[k] = sx / Mx[k][k];  thy[k] = sy / Mx[k][k];
        }
        // reference reconstructs w0 = -sum(theta[1..8])
        float s8x = 0.f, s8y = 0.f;
        for (int c = 1; c < 9; ++c) { s8x += thx[c]; s8y += thy[c]; }
        swx[0] = -s8x; swy[0] = -s8y;
        for (int c = 1; c < 9; ++c) { swx[c] = thx[c]; swy[c] = thy[c]; }
        sax[0] = thx[9]; sax[1] = thx[10]; sax[2] = thx[11];
        say[0] = thy[9]; say[1] = thy[10]; say[2] = thy[11];
        for (int c = 0; c < 9; ++c) { sdx[c] = dx9[c]; sdy[c] = dy9[c]; }
    }
    __syncthreads();

    int r = tid >> 4, c = tid & 15;             // grid point (row r, col c), kl = tid
    float px = c * (1.f / 15.f), py = r * (1.f / 15.f);
    float zx = 0.f, zy = 0.f;
    #pragma unroll
    for (int q = 0; q < 9; ++q) {
        float ddx = px - sdx[q], ddy = py - sdy[q];
        float rr = sqrtf(ddx * ddx + ddy * ddy + 1e-12f);
        float u = rr * rr * logf(rr + 1e-6f);
        zx += u * swx[q]; zy += u * swy[q];
    }
    zx += sax[0] + px * sax[1] + py * sax[2];
    zy += say[0] + px * say[1] + py * say[2];
    float axv = (px + zx) * 15.f;
    float ayv = (py + zy) * 15.f;

    const float* col = corr + (size_t)b * 65536 + tid;   // column kl, stride 256
    float s = 0.f;
    for (int i = 0; i < 16; ++i) {
        if (fabsf((float)i - ayv) > 1.f) continue;
        const float* rp = col + i * 4096;
        for (int j = 0; j < 16; ++j)
            if (fabsf((float)j - axv) <= 1.f) s += rp[j * 256];
    }
    red[tid] = s;
    __syncthreads();
    for (int o = 128; o > 0; o >>= 1) {
        if (tid < o) red[tid] += red[tid + o];
        __syncthreads();
    }
    if (tid == 0) out[b] = red[0];
}

// ---------------- launch ------------------------------------------------------
extern "C" void kernel_launch(void* const* d_in, const int* in_sizes, int n_in,
                              void* d_out, int out_size)
{
    const float* imgA = (const float*)d_in[0];
    const float* imgB = (const float*)d_in[1];
    const float* W1   = (const float*)d_in[2];
    const float* W2   = (const float*)d_in[3];
    const float* W3   = (const float*)d_in[4];
    const float* W4   = (const float*)d_in[5];
    const float* Wr1  = (const float*)d_in[6];
    const float* Wr2  = (const float*)d_in[7];
    const float* Wd   = (const float*)d_in[8];
    const float* bd   = (const float*)d_in[9];
    float* out = (float*)d_out;

    float *buf1, *buf2, *buf3, *featA, *featB, *corr, *r1, *r2, *geo;
    cudaGetSymbolAddress((void**)&buf1,  g_buf1);
    cudaGetSymbolAddress((void**)&buf2,  g_buf2);
    cudaGetSymbolAddress((void**)&buf3,  g_buf3);
    cudaGetSymbolAddress((void**)&featA, g_featA);
    cudaGetSymbolAddress((void**)&featB, g_featB);
    cudaGetSymbolAddress((void**)&corr,  g_corr);
    cudaGetSymbolAddress((void**)&r1,    g_r1);
    cudaGetSymbolAddress((void**)&r2,    g_r2);
    cudaGetSymbolAddress((void**)&geo,   g_geo);

    for (int im = 0; im < 2; ++im) {
        const float* img = im ? imgB : imgA;
        float* feat = im ? featB : featA;
        // 32*128*128*64 = 33,554,432 outputs -> 131072 blocks (was 2x too big: OOB)
        conv1_kernel<<<131072, 256>>>(img, W1, buf1);
        conv_igemm<64, 128, 128, 128, 64, 64, 3, 3, 2, false>
            <<<dim3(64, 2, 32), 256>>>(buf1, W2, buf2);
        conv_igemm<128, 256, 64, 64, 32, 32, 3, 3, 2, false>
            <<<dim3(16, 4, 32), 256>>>(buf2, W3, buf3);
        conv_igemm<256, 512, 32, 32, 16, 16, 3, 3, 2, false>
            <<<dim3(4, 8, 32), 256>>>(buf3, W4, feat);
        normalize_kernel<<<8192, 128>>>(feat);
    }

    corr_kernel<<<dim3(4, 4, 32), 256>>>(featA, featB, corr);

    conv_igemm<256, 128, 16, 16, 10, 10, 7, 7, 1, true>
        <<<dim3(2, 2, 32), 256>>>(corr, Wr1, r1);
    conv_igemm<128, 64, 10, 10, 6, 6, 5, 5, 1, true>
        <<<dim3(1, 1, 32), 256>>>(r1, Wr2, r2);

    dense_kernel<<<32, 576>>>(r2, Wd, bd, geo);
    tps_sum_kernel<<<32, 256>>>(geo, corr, out);
}